// round 2
// baseline (speedup 1.0000x reference)
#include <cuda_runtime.h>
#include <math.h>

#define R_TOT 2048   // B*C rows
#define N0 8192
#define M1 4099
#define M2 2053
#define M3 1030
#define M4 518
#define CB 64
#define BB 32

__constant__ float c_dlo[8] = {-0.010597401784997278f, 0.032883011666982945f, 0.030841381835986965f,
                               -0.18703481171888114f, -0.02798376941698385f, 0.6308807679295904f,
                               0.7148465705525415f, 0.23037781330885523f};
__constant__ float c_dhi[8] = {-0.23037781330885523f, 0.7148465705525415f, -0.6308807679295904f,
                               -0.02798376941698385f, 0.18703481171888114f, 0.030841381835986965f,
                               -0.032883011666982945f, -0.010597401784997278f};

// Scratch (static device globals; allocation-free per harness rules)
__device__ float g_xt[(size_t)R_TOT * N0];   // transposed input; reused as final y
__device__ float g_a1[(size_t)R_TOT * M1];
__device__ float g_d1[(size_t)R_TOT * M1];
__device__ float g_a2[(size_t)R_TOT * M2];
__device__ float g_d2[(size_t)R_TOT * M2];
__device__ float g_a3[(size_t)R_TOT * M3];
__device__ float g_d3[(size_t)R_TOT * M3];
__device__ float g_a4[(size_t)R_TOT * M4];
__device__ float g_d4[(size_t)R_TOT * M4];
__device__ float g_a4m[(size_t)R_TOT * M4];
__device__ float g_d4m[(size_t)R_TOT * M4];

// ---------------------------------------------------------------------------
// Transpose: x (B, N, C) -> xt (B*C, N)
// ---------------------------------------------------------------------------
__global__ void transpose_kernel(const float* __restrict__ x, float* __restrict__ xt) {
    __shared__ float tile[32][33];
    int b = blockIdx.z;
    int n0 = blockIdx.x * 32;
    int c0 = blockIdx.y * 32;
    int tx = threadIdx.x, ty = threadIdx.y;  // 32 x 8
#pragma unroll
    for (int i = 0; i < 32; i += 8)
        tile[ty + i][tx] = x[((size_t)b * N0 + n0 + ty + i) * CB + c0 + tx];
    __syncthreads();
#pragma unroll
    for (int i = 0; i < 32; i += 8)
        xt[((size_t)b * CB + c0 + ty + i) * N0 + n0 + tx] = tile[tx][ty + i];
}

// ---------------------------------------------------------------------------
// One DWT level: in (R, n) -> a, d (R, m), m = (n+7)/2, pywt symmetric mode
// y[k] = sum_j filt[j] * x_sym[2k+1-j]
// ---------------------------------------------------------------------------
__global__ void dwt_kernel(const float* __restrict__ in, float* __restrict__ a,
                           float* __restrict__ d, int n, int m) {
    int row = blockIdx.y;
    int k = blockIdx.x * blockDim.x + threadIdx.x;
    if (k >= m) return;
    const float* __restrict__ x = in + (size_t)row * n;
    int base = 2 * k + 1;
    float sa = 0.f, sd = 0.f;
#pragma unroll
    for (int j = 0; j < 8; j++) {
        int p = base - j;
        p = (p < 0) ? (-1 - p) : p;
        p = (p >= n) ? (2 * n - 1 - p) : p;
        float v = __ldg(&x[p]);
        sa = fmaf(v, c_dlo[j], sa);
        sd = fmaf(v, c_dhi[j], sd);
    }
    a[(size_t)row * m + k] = sa;
    d[(size_t)row * m + k] = sd;
}

// ---------------------------------------------------------------------------
// One IDWT level: ca, cd (R, m) -> out (R, out_len)
// p even: sum_s ca[r+s]*dec_lo[1+2s] + cd[r+s]*dec_hi[1+2s]
// p odd : sum_s ca[r+s]*dec_lo[2s]   + cd[r+s]*dec_hi[2s]      (r = p>>1)
// Length arithmetic guarantees r+3 < m, r >= 0: no bounds checks.
// ---------------------------------------------------------------------------
__global__ void idwt_kernel(const float* __restrict__ ca, const float* __restrict__ cd,
                            float* __restrict__ out, int m, int out_len) {
    int row = blockIdx.y;
    int p = blockIdx.x * blockDim.x + threadIdx.x;
    if (p >= out_len) return;
    const float* __restrict__ A = ca + (size_t)row * m;
    const float* __restrict__ D = cd + (size_t)row * m;
    int r = p >> 1;
    float s = 0.f;
    if (p & 1) {
#pragma unroll
        for (int t = 0; t < 4; t++)
            s = fmaf(__ldg(&A[r + t]), c_dlo[2 * t], fmaf(__ldg(&D[r + t]), c_dhi[2 * t], s));
    } else {
#pragma unroll
        for (int t = 0; t < 4; t++)
            s = fmaf(__ldg(&A[r + t]), c_dlo[2 * t + 1], fmaf(__ldg(&D[r + t]), c_dhi[2 * t + 1], s));
    }
    out[(size_t)row * out_len + p] = s;
}

// ---------------------------------------------------------------------------
// Channel mix at coarsest level: out[b*64+o, k] = sum_i in[b*64+i, k] * w[i,o,k]
// One block per k (grid.y selects (a4,w1) vs (d4,w2)). w slice + input column in SMEM.
// ---------------------------------------------------------------------------
__global__ void mix_kernel(const float* __restrict__ a4, const float* __restrict__ d4,
                           const float* __restrict__ w1, const float* __restrict__ w2,
                           float* __restrict__ a4m, float* __restrict__ d4m) {
    const int m = M4;
    int k = blockIdx.x;
    const float* __restrict__ in = blockIdx.y ? d4 : a4;
    const float* __restrict__ w = blockIdx.y ? w2 : w1;
    float* __restrict__ out = blockIdx.y ? d4m : a4m;

    __shared__ __align__(16) float ws[4096];  // ws[i*64+o] = w[i,o,k]
    __shared__ float as[32 * 65];             // as[b*65+i] = in[b*64+i, k]
    int tid = threadIdx.x;
    for (int idx = tid; idx < 4096; idx += 256)
        ws[idx] = __ldg(&w[(size_t)idx * m + k]);
    for (int idx = tid; idx < 2048; idx += 256) {
        int b = idx >> 6, i = idx & 63;
        as[b * 65 + i] = __ldg(&in[(size_t)idx * m + k]);
    }
    __syncthreads();

    int b = tid >> 3;
    int og = (tid & 7) * 8;
    const float4* ws4 = reinterpret_cast<const float4*>(ws);
    float4 acc0 = make_float4(0.f, 0.f, 0.f, 0.f);
    float4 acc1 = make_float4(0.f, 0.f, 0.f, 0.f);
#pragma unroll
    for (int i = 0; i < 64; i++) {
        float av = as[b * 65 + i];
        float4 w0 = ws4[i * 16 + (og >> 2)];
        float4 wv = ws4[i * 16 + (og >> 2) + 1];
        acc0.x = fmaf(av, w0.x, acc0.x); acc0.y = fmaf(av, w0.y, acc0.y);
        acc0.z = fmaf(av, w0.z, acc0.z); acc0.w = fmaf(av, w0.w, acc0.w);
        acc1.x = fmaf(av, wv.x, acc1.x); acc1.y = fmaf(av, wv.y, acc1.y);
        acc1.z = fmaf(av, wv.z, acc1.z); acc1.w = fmaf(av, wv.w, acc1.w);
    }
    size_t ob = (size_t)(b * 64 + og) * m + k;
    out[ob]           = acc0.x; out[ob + (size_t)m]     = acc0.y;
    out[ob + 2ull*m]  = acc0.z; out[ob + 3ull*m]        = acc0.w;
    out[ob + 4ull*m]  = acc1.x; out[ob + 5ull*m]        = acc1.y;
    out[ob + 6ull*m]  = acc1.z; out[ob + 7ull*m]        = acc1.w;
}

// ---------------------------------------------------------------------------
// Final: out[b,n,c] = mish( y[b*64+c, n] + (x[b,n,:] @ dk)[c] + bias[c] )
// Block = (b, 32-wide n-tile). Transposing y read via SMEM; dk staged in SMEM.
// ---------------------------------------------------------------------------
__device__ __forceinline__ float mish_f(float v) {
    float sp = (v > 20.f) ? v : log1pf(expf(v));
    return v * tanhf(sp);
}

__global__ void final_kernel(const float* __restrict__ y, const float* __restrict__ x,
                             const float* __restrict__ dk, const float* __restrict__ bias,
                             float* __restrict__ out) {
    int b = blockIdx.y;
    int n0 = blockIdx.x * 32;
    __shared__ __align__(16) float dks[4096];  // dks[i*64+o]
    __shared__ float xs[32 * 65];              // xs[nn*65+i]
    __shared__ float ys[32 * 65];              // ys[nn*65+c]
    __shared__ float bs[64];
    int tid = threadIdx.x;
    for (int idx = tid; idx < 4096; idx += 256) dks[idx] = __ldg(&dk[idx]);
    if (tid < 64) bs[tid] = __ldg(&bias[tid]);
    for (int idx = tid; idx < 2048; idx += 256) {
        int c = idx >> 5, nn = idx & 31;
        ys[nn * 65 + c] = __ldg(&y[((size_t)b * CB + c) * N0 + n0 + nn]);
    }
    for (int idx = tid; idx < 2048; idx += 256) {
        int nn = idx >> 6, i = idx & 63;
        xs[nn * 65 + i] = __ldg(&x[((size_t)b * N0 + n0 + nn) * CB + i]);
    }
    __syncthreads();

    int nn = tid >> 3;
    int cg = (tid & 7) * 8;
    const float4* dk4 = reinterpret_cast<const float4*>(dks);
    float4 acc0 = make_float4(bs[cg], bs[cg + 1], bs[cg + 2], bs[cg + 3]);
    float4 acc1 = make_float4(bs[cg + 4], bs[cg + 5], bs[cg + 6], bs[cg + 7]);
#pragma unroll
    for (int i = 0; i < 64; i++) {
        float xv = xs[nn * 65 + i];
        float4 w0 = dk4[i * 16 + (cg >> 2)];
        float4 wv = dk4[i * 16 + (cg >> 2) + 1];
        acc0.x = fmaf(xv, w0.x, acc0.x); acc0.y = fmaf(xv, w0.y, acc0.y);
        acc0.z = fmaf(xv, w0.z, acc0.z); acc0.w = fmaf(xv, w0.w, acc0.w);
        acc1.x = fmaf(xv, wv.x, acc1.x); acc1.y = fmaf(xv, wv.y, acc1.y);
        acc1.z = fmaf(xv, wv.z, acc1.z); acc1.w = fmaf(xv, wv.w, acc1.w);
    }
    float vals[8] = {acc0.x, acc0.y, acc0.z, acc0.w, acc1.x, acc1.y, acc1.z, acc1.w};
#pragma unroll
    for (int u = 0; u < 8; u++) {
        float v = vals[u] + ys[nn * 65 + cg + u];
        vals[u] = mish_f(v);
    }
    float4* op = reinterpret_cast<float4*>(&out[((size_t)b * N0 + n0 + nn) * CB + cg]);
    op[0] = make_float4(vals[0], vals[1], vals[2], vals[3]);
    op[1] = make_float4(vals[4], vals[5], vals[6], vals[7]);
}

// ---------------------------------------------------------------------------
extern "C" void kernel_launch(void* const* d_in, const int* in_sizes, int n_in,
                              void* d_out, int out_size) {
    (void)in_sizes; (void)n_in; (void)out_size;
    const float* x    = (const float*)d_in[0];
    const float* w1   = (const float*)d_in[1];
    const float* w2   = (const float*)d_in[2];
    const float* dk   = (const float*)d_in[3];
    const float* bias = (const float*)d_in[4];
    float* out = (float*)d_out;

    float *xt, *a1, *d1, *a2, *d2, *a3, *d3, *a4, *d4, *a4m, *d4m;
    cudaGetSymbolAddress((void**)&xt,  g_xt);
    cudaGetSymbolAddress((void**)&a1,  g_a1);
    cudaGetSymbolAddress((void**)&d1,  g_d1);
    cudaGetSymbolAddress((void**)&a2,  g_a2);
    cudaGetSymbolAddress((void**)&d2,  g_d2);
    cudaGetSymbolAddress((void**)&a3,  g_a3);
    cudaGetSymbolAddress((void**)&d3,  g_d3);
    cudaGetSymbolAddress((void**)&a4,  g_a4);
    cudaGetSymbolAddress((void**)&d4,  g_d4);
    cudaGetSymbolAddress((void**)&a4m, g_a4m);
    cudaGetSymbolAddress((void**)&d4m, g_d4m);

    // 1. transpose x -> xt
    transpose_kernel<<<dim3(N0 / 32, CB / 32, BB), dim3(32, 8)>>>(x, xt);
    // 2. analysis (4 DWT levels)
    dwt_kernel<<<dim3((M1 + 255) / 256, R_TOT), 256>>>(xt, a1, d1, N0, M1);
    dwt_kernel<<<dim3((M2 + 255) / 256, R_TOT), 256>>>(a1, a2, d2, M1, M2);
    dwt_kernel<<<dim3((M3 + 255) / 256, R_TOT), 256>>>(a2, a3, d3, M2, M3);
    dwt_kernel<<<dim3((M4 + 255) / 256, R_TOT), 256>>>(a3, a4, d4, M3, M4);
    // 3. channel mixing on coarsest a/d
    mix_kernel<<<dim3(M4, 2), 256>>>(a4, d4, w1, w2, a4m, d4m);
    // 4. synthesis (4 IDWT levels), reusing buffers
    idwt_kernel<<<dim3((M3 + 255) / 256, R_TOT), 256>>>(a4m, d4m, a3, M4, M3);
    idwt_kernel<<<dim3((M2 + 255) / 256, R_TOT), 256>>>(a3, d3, a2, M3, M2);
    idwt_kernel<<<dim3((M1 + 255) / 256, R_TOT), 256>>>(a2, d2, a1, M2, M1);
    idwt_kernel<<<dim3(N0 / 256, R_TOT), 256>>>(a1, d1, xt, M1, N0);
    // 5. fused transpose-back + dense shortcut + mish
    final_kernel<<<dim3(N0 / 32, BB), 256>>>(xt, x, dk, bias, out);
}